// round 10
// baseline (speedup 1.0000x reference)
#include <cuda_runtime.h>
#include <math.h>

#define B_   2
#define HGT  128
#define WID  128
#define C_   128
#define NWIN 64          // 8x8 windows
#define WT   256         // tokens per window (16x16)
#define LTOK (HGT*WID)   // 16384
#define MT   (B_*LTOK)   // 32768
#define HID_ 1024
#define SCALE 0.08838834764831845f  // 1/sqrt(128)

#define PAD  20          // smem row stride (floats)
#define BK   16
#define TSZ  (128*PAD)   // one smem tile buffer (floats)

// ---------------- device scratch ----------------
static __device__ float g_q [MT*C_];
static __device__ float g_k [MT*C_];
static __device__ float g_v [MT*C_];
static __device__ float g_sc[(size_t)B_*NWIN*WT*WT];
static __device__ float g_ao[MT*C_];
static __device__ float g_t1[MT*C_];
static __device__ float g_msg[MT*C_];
static __device__ float g_hid[(size_t)MT*HID_];

__device__ __forceinline__ int tok_off(int b, int n, int i) {
    int wy = n >> 3, wx = n & 7;
    int gh = ((wy << 4) + (i >> 4) + 8) & 127;
    int gw = ((wx << 4) + (i & 15) + 8) & 127;
    return ((b * HGT + gh) * WID + gw) * C_;
}

__device__ __forceinline__ float tf32r(float x) {
    unsigned u; asm("cvt.rna.tf32.f32 %0, %1;" : "=r"(u) : "f"(x));
    return __uint_as_float(u);
}

// ============================================================================
// smem k-permutation: within each 8-wide k group, element k sits at
// k' = (k&3)*2 + (k>>2).  Fragment pair (c, c+4) -> adjacent -> LDS.64.
// ============================================================================

// ---------------- mma compute: 2 ksteps (k8) over current buffers ----------------
__device__ __forceinline__ void mma_compute(const float* __restrict__ As,
                                            const float* __restrict__ Bs,
                                            float (&acc)[4][4][4],
                                            int wm0, int wn0, int lane)
{
    const int r = lane >> 2, c2 = (lane & 3) * 2;
    #pragma unroll
    for (int ks = 0; ks < 2; ++ks) {
        const int kb = ks * 8 + c2;
        unsigned a[4][4], bf[4][2];
        #pragma unroll
        for (int mt = 0; mt < 4; ++mt) {
            const float* p = As + (wm0 + mt*16 + r)*PAD + kb;
            float2 lo = *(const float2*)p;
            float2 hi = *(const float2*)(p + 8*PAD);
            a[mt][0] = __float_as_uint(lo.x);
            a[mt][1] = __float_as_uint(hi.x);
            a[mt][2] = __float_as_uint(lo.y);
            a[mt][3] = __float_as_uint(hi.y);
        }
        #pragma unroll
        for (int nt = 0; nt < 4; ++nt) {
            const float* p = Bs + (wn0 + nt*8 + r)*PAD + kb;
            float2 bb = *(const float2*)p;
            bf[nt][0] = __float_as_uint(bb.x);
            bf[nt][1] = __float_as_uint(bb.y);
        }
        #pragma unroll
        for (int mt = 0; mt < 4; ++mt)
            #pragma unroll
            for (int nt = 0; nt < 4; ++nt)
                asm volatile(
                  "mma.sync.aligned.m16n8k8.row.col.f32.tf32.tf32.f32 "
                  "{%0,%1,%2,%3},{%4,%5,%6,%7},{%8,%9},{%0,%1,%2,%3};"
                  : "+f"(acc[mt][nt][0]), "+f"(acc[mt][nt][1]),
                    "+f"(acc[mt][nt][2]), "+f"(acc[mt][nt][3])
                  : "r"(a[mt][0]), "r"(a[mt][1]), "r"(a[mt][2]), "r"(a[mt][3]),
                    "r"(bf[nt][0]), "r"(bf[nt][1]));
    }
}

// ---------------- loaders / smem stores ----------------
__device__ __forceinline__ void ldA(const float* __restrict__ A, int lda, int k0,
                                    int tid, float4& v0, float4& v1) {
    const float* p = A + (size_t)(tid >> 1) * lda + k0 + (tid & 1) * 8;
    v0 = *(const float4*)p; v1 = *(const float4*)(p + 4);
}
__device__ __forceinline__ void ldA_gather(const float* __restrict__ X, const int* __restrict__ off,
                                           int k0, int tid, float4& v0, float4& v1) {
    const float* p = X + off[tid >> 1] + k0 + (tid & 1) * 8;
    v0 = *(const float4*)p; v1 = *(const float4*)(p + 4);
}
// store row-major 8 k-values at permuted positions (v0 = k 0..3 -> slots 0,2,4,6;
// v1 = k 4..7 -> slots 1,3,5,7)
__device__ __forceinline__ void stA(float* __restrict__ S, int tid, float4 v0, float4 v1) {
    float* p = S + (tid >> 1) * PAD + (tid & 1) * 8;
    p[0]=tf32r(v0.x); p[2]=tf32r(v0.y); p[4]=tf32r(v0.z); p[6]=tf32r(v0.w);
    p[1]=tf32r(v1.x); p[3]=tf32r(v1.y); p[5]=tf32r(v1.z); p[7]=tf32r(v1.w);
}
// B transpose tile (gmem [K][N] -> smem [n][k'] permuted)
__device__ __forceinline__ void ldBT(const float* __restrict__ B, int ldb, int k0, int bn0,
                                     int tid, float rb[8]) {
    const int kr = tid >> 5, lane = tid & 31;
    const float* p0 = B + (size_t)(k0 + kr)     * ldb + bn0 + lane;
    const float* p1 = B + (size_t)(k0 + kr + 8) * ldb + bn0 + lane;
    #pragma unroll
    for (int i = 0; i < 4; ++i) { rb[i] = p0[32*i]; rb[4+i] = p1[32*i]; }
}
__device__ __forceinline__ void ldBT_gather(const float* __restrict__ V, const int* __restrict__ off,
                                            int k0, int tid, float rb[8]) {
    const int kr = tid >> 5, lane = tid & 31;
    const float* p0 = V + off[k0 + kr]     + lane;
    const float* p1 = V + off[k0 + kr + 8] + lane;
    #pragma unroll
    for (int i = 0; i < 4; ++i) { rb[i] = p0[32*i]; rb[4+i] = p1[32*i]; }
}
__device__ __forceinline__ void stBT(float* __restrict__ S, int tid, const float rb[8]) {
    const int kr = tid >> 5, lane = tid & 31;
    const int kp = (kr & 3) * 2 + (kr >> 2);
    #pragma unroll
    for (int i = 0; i < 4; ++i) {
        S[(lane + 32*i)*PAD + kp    ] = tf32r(rb[i]);
        S[(lane + 32*i)*PAD + 8 + kp] = tf32r(rb[4+i]);
    }
}

// ---------------- plain store ----------------
__device__ __forceinline__ void store_plain(float* __restrict__ Cg, int ldc, int bm0, int bn0,
                                            const float (&acc)[4][4][4], int wm0, int wn0, int lane)
{
    const int r = lane >> 2, q2 = (lane & 3) * 2;
    #pragma unroll
    for (int mt = 0; mt < 4; ++mt) {
        const int row = bm0 + wm0 + mt*16 + r;
        #pragma unroll
        for (int nt = 0; nt < 4; ++nt) {
            const int col = bn0 + wn0 + nt*8 + q2;
            *(float2*)&Cg[(size_t)row * ldc + col]       = make_float2(acc[mt][nt][0], acc[mt][nt][1]);
            *(float2*)&Cg[(size_t)(row + 8) * ldc + col] = make_float2(acc[mt][nt][2], acc[mt][nt][3]);
        }
    }
}

// ---------------- generic GEMM C = A(MxK) @ B(KxN), tf32 ----------------
__global__ __launch_bounds__(256) void gemm_tf32(
    const float* __restrict__ A, const float* __restrict__ B, float* __restrict__ Cg,
    int N, int K)
{
    __shared__ __align__(16) float As2[2*TSZ], Bs2[2*TSZ];
    const int tid = threadIdx.x, lane = tid & 31, wid = tid >> 5;
    const int wm0 = (wid >> 2) * 64, wn0 = (wid & 3) * 32;
    const int bm0 = blockIdx.y * 128, bn0 = blockIdx.x * 128;
    const float* Ab = A + (size_t)bm0 * K;
    float acc[4][4][4] = {};
    float4 a0, a1; float rb[8];

    ldA(Ab, K, 0, tid, a0, a1); ldBT(B, N, 0, bn0, tid, rb);
    stA(As2, tid, a0, a1); stBT(Bs2, tid, rb);
    __syncthreads();
    int buf = 0;
    for (int k0 = BK; k0 < K; k0 += BK) {
        ldA(Ab, K, k0, tid, a0, a1); ldBT(B, N, k0, bn0, tid, rb);
        mma_compute(As2 + buf*TSZ, Bs2 + buf*TSZ, acc, wm0, wn0, lane);
        stA(As2 + (buf^1)*TSZ, tid, a0, a1); stBT(Bs2 + (buf^1)*TSZ, tid, rb);
        __syncthreads();
        buf ^= 1;
    }
    mma_compute(As2 + buf*TSZ, Bs2 + buf*TSZ, acc, wm0, wn0, lane);
    store_plain(Cg, N, bm0, bn0, acc, wm0, wn0, lane);
}

// ---------------- QKV: z selects (A, W, O) ----------------
__global__ __launch_bounds__(256) void qkv_tf32(
    const float* __restrict__ src, const float* __restrict__ tgt,
    const float* __restrict__ Wq, const float* __restrict__ Wk, const float* __restrict__ Wv)
{
    __shared__ __align__(16) float As2[2*TSZ], Bs2[2*TSZ];
    const int z = blockIdx.z;
    const float* A = (z == 0) ? src : tgt;
    const float* W = (z == 0) ? Wq : (z == 1 ? Wk : Wv);
    float* O = (z == 0) ? g_q : (z == 1 ? g_k : g_v);

    const int tid = threadIdx.x, lane = tid & 31, wid = tid >> 5;
    const int wm0 = (wid >> 2) * 64, wn0 = (wid & 3) * 32;
    const int bm0 = blockIdx.y * 128;
    const float* Ab = A + (size_t)bm0 * C_;
    float acc[4][4][4] = {};
    float4 a0, a1; float rb[8];

    ldA(Ab, C_, 0, tid, a0, a1); ldBT(W, C_, 0, 0, tid, rb);
    stA(As2, tid, a0, a1); stBT(Bs2, tid, rb);
    __syncthreads();
    int buf = 0;
    for (int k0 = BK; k0 < C_; k0 += BK) {
        ldA(Ab, C_, k0, tid, a0, a1); ldBT(W, C_, k0, 0, tid, rb);
        mma_compute(As2 + buf*TSZ, Bs2 + buf*TSZ, acc, wm0, wn0, lane);
        stA(As2 + (buf^1)*TSZ, tid, a0, a1); stBT(Bs2 + (buf^1)*TSZ, tid, rb);
        __syncthreads();
        buf ^= 1;
    }
    mma_compute(As2 + buf*TSZ, Bs2 + buf*TSZ, acc, wm0, wn0, lane);
    store_plain(O, C_, bm0, 0, acc, wm0, wn0, lane);
}

// ---------------- window scores: S = Qw Kw^T * scale + mask ----------------
__global__ __launch_bounds__(256) void win_scores_tf32(const float* __restrict__ mask)
{
    __shared__ __align__(16) float As2[2*TSZ], Bs2[2*TSZ];
    __shared__ int offQ[128], offK[128];
    const int bw = blockIdx.z, b = bw >> 6, n = bw & 63;
    const int bi0 = blockIdx.y * 128, bj0 = blockIdx.x * 128;
    const int tid = threadIdx.x, lane = tid & 31, wid = tid >> 5;
    const int wm0 = (wid >> 2) * 64, wn0 = (wid & 3) * 32;

    if (tid < 128) offQ[tid] = tok_off(b, n, bi0 + tid);
    else           offK[tid - 128] = tok_off(b, n, bj0 + tid - 128);
    __syncthreads();

    float acc[4][4][4] = {};
    float4 a0, a1, b0, b1;
    ldA_gather(g_q, offQ, 0, tid, a0, a1);
    ldA_gather(g_k, offK, 0, tid, b0, b1);
    stA(As2, tid, a0, a1); stA(Bs2, tid, b0, b1);   // K stored [n][k'] directly
    __syncthreads();
    int buf = 0;
    for (int k0 = BK; k0 < C_; k0 += BK) {
        ldA_gather(g_q, offQ, k0, tid, a0, a1);
        ldA_gather(g_k, offK, k0, tid, b0, b1);
        mma_compute(As2 + buf*TSZ, Bs2 + buf*TSZ, acc, wm0, wn0, lane);
        stA(As2 + (buf^1)*TSZ, tid, a0, a1); stA(Bs2 + (buf^1)*TSZ, tid, b0, b1);
        __syncthreads();
        buf ^= 1;
    }
    mma_compute(As2 + buf*TSZ, Bs2 + buf*TSZ, acc, wm0, wn0, lane);

    const int r = lane >> 2, q2 = (lane & 3) * 2;
    #pragma unroll
    for (int mt = 0; mt < 4; ++mt) {
        #pragma unroll
        for (int nt = 0; nt < 4; ++nt) {
            const int col = bj0 + wn0 + nt*8 + q2;
            #pragma unroll
            for (int hh = 0; hh < 2; ++hh) {
                const int row = bi0 + wm0 + mt*16 + r + hh*8;
                const size_t sidx = ((size_t)bw * WT + row) * WT + col;
                const size_t midx = ((size_t)n  * WT + row) * WT + col;
                float2 mk = *(const float2*)&mask[midx];
                float2 o  = make_float2(acc[mt][nt][2*hh]   * SCALE + mk.x,
                                        acc[mt][nt][2*hh+1] * SCALE + mk.y);
                *(float2*)&g_sc[sidx] = o;
            }
        }
    }
}

// ---------------- O = P @ Vw, scatter-unshift on store ----------------
__global__ __launch_bounds__(256) void win_av_tf32()
{
    __shared__ __align__(16) float As2[2*TSZ], Bs2[2*TSZ];
    __shared__ int offV[256];
    const int bw = blockIdx.z, b = bw >> 6, n = bw & 63;
    const int bi0 = blockIdx.y * 128;
    const int tid = threadIdx.x, lane = tid & 31, wid = tid >> 5;
    const int wm0 = (wid >> 2) * 64, wn0 = (wid & 3) * 32;

    offV[tid] = tok_off(b, n, tid);
    __syncthreads();

    const float* P = g_sc + ((size_t)bw * WT + bi0) * WT;  // [128][256]
    float acc[4][4][4] = {};
    float4 a0, a1; float rb[8];
    ldA(P, WT, 0, tid, a0, a1); ldBT_gather(g_v, offV, 0, tid, rb);
    stA(As2, tid, a0, a1); stBT(Bs2, tid, rb);
    __syncthreads();
    int buf = 0;
    for (int k0 = BK; k0 < WT; k0 += BK) {
        ldA(P, WT, k0, tid, a0, a1); ldBT_gather(g_v, offV, k0, tid, rb);
        mma_compute(As2 + buf*TSZ, Bs2 + buf*TSZ, acc, wm0, wn0, lane);
        stA(As2 + (buf^1)*TSZ, tid, a0, a1); stBT(Bs2 + (buf^1)*TSZ, tid, rb);
        __syncthreads();
        buf ^= 1;
    }
    mma_compute(As2 + buf*TSZ, Bs2 + buf*TSZ, acc, wm0, wn0, lane);

    const int r = lane >> 2, q2 = (lane & 3) * 2;
    #pragma unroll
    for (int mt = 0; mt < 4; ++mt) {
        #pragma unroll
        for (int hh = 0; hh < 2; ++hh) {
            const int lrow = wm0 + mt*16 + r + hh*8;
            const int ro = offV[bi0 + lrow];
            #pragma unroll
            for (int nt = 0; nt < 4; ++nt) {
                const int col = wn0 + nt*8 + q2;
                *(float2*)&g_ao[ro + col] =
                    make_float2(acc[mt][nt][2*hh], acc[mt][nt][2*hh+1]);
            }
        }
    }
}

// ---------------- FFN1: H = gelu([src|msg] @ W1) ----------------
__global__ __launch_bounds__(256) void ffn1_tf32(
    const float* __restrict__ src, const float* __restrict__ W1)
{
    __shared__ __align__(16) float As2[2*TSZ], Bs2[2*TSZ];
    const int tid = threadIdx.x, lane = tid & 31, wid = tid >> 5;
    const int wm0 = (wid >> 2) * 64, wn0 = (wid & 3) * 32;
    const int bm0 = blockIdx.y * 128, bn0 = blockIdx.x * 128;
    const float* A0 = src   + (size_t)bm0 * C_;
    const float* A1 = g_msg + (size_t)bm0 * C_;
    float acc[4][4][4] = {};
    float4 a0, a1; float rb[8];

    ldA(A0, C_, 0, tid, a0, a1); ldBT(W1, HID_, 0, bn0, tid, rb);
    stA(As2, tid, a0, a1); stBT(Bs2, tid, rb);
    __syncthreads();
    int buf = 0;
    for (int k0 = BK; k0 < 2*C_; k0 += BK) {
        const float* Ae = (k0 < C_) ? A0 : A1;
        ldA(Ae, C_, k0 & (C_-1), tid, a0, a1);
        ldBT(W1, HID_, k0, bn0, tid, rb);
        mma_compute(As2 + buf*TSZ, Bs2 + buf*TSZ, acc, wm0, wn0, lane);
        stA(As2 + (buf^1)*TSZ, tid, a0, a1); stBT(Bs2 + (buf^1)*TSZ, tid, rb);
        __syncthreads();
        buf ^= 1;
    }
    mma_compute(As2 + buf*TSZ, Bs2 + buf*TSZ, acc, wm0, wn0, lane);

    const int r = lane >> 2, q2 = (lane & 3) * 2;
    #pragma unroll
    for (int mt = 0; mt < 4; ++mt) {
        #pragma unroll
        for (int nt = 0; nt < 4; ++nt) {
            const int col = bn0 + wn0 + nt*8 + q2;
            #pragma unroll
            for (int hh = 0; hh < 2; ++hh) {
                const int row = bm0 + wm0 + mt*16 + r + hh*8;
                float x0 = acc[mt][nt][2*hh], x1 = acc[mt][nt][2*hh+1];
                float gg0 = 0.5f * x0 * (1.0f + erff(x0 * 0.70710678118654752f));
                float gg1 = 0.5f * x1 * (1.0f + erff(x1 * 0.70710678118654752f));
                *(float2*)&g_hid[(size_t)row * HID_ + col] = make_float2(gg0, gg1);
            }
        }
    }
}

// ---------------- warp-per-row softmax over 256 (in place) ----------------
__global__ __launch_bounds__(256) void softmax_warp(float* __restrict__ sc) {
    const int row  = blockIdx.x * 8 + (threadIdx.x >> 5);
    const int lane = threadIdx.x & 31;
    float* p = sc + (size_t)row * WT + lane * 8;
    float4 x0 = *(const float4*)p;
    float4 x1 = *(const float4*)(p + 4);
    float m = fmaxf(fmaxf(fmaxf(x0.x, x0.y), fmaxf(x0.z, x0.w)),
                    fmaxf(fmaxf(x1.x, x1.y), fmaxf(x1.z, x1.w)));
    #pragma unroll
    for (int s = 16; s > 0; s >>= 1) m = fmaxf(m, __shfl_xor_sync(0xffffffffu, m, s));
    x0.x = __expf(x0.x - m); x0.y = __expf(x0.y - m);
    x0.z = __expf(x0.z - m); x0.w = __expf(x0.w - m);
    x1.x = __expf(x1.x - m); x1.y = __expf(x1.y - m);
    x1.z = __expf(x1.z - m); x1.w = __expf(x1.w - m);
    float sum = x0.x + x0.y + x0.z + x0.w + x1.x + x1.y + x1.z + x1.w;
    #pragma unroll
    for (int s = 16; s > 0; s >>= 1) sum += __shfl_xor_sync(0xffffffffu, sum, s);
    const float inv = 1.0f / sum;
    x0.x *= inv; x0.y *= inv; x0.z *= inv; x0.w *= inv;
    x1.x *= inv; x1.y *= inv; x1.z *= inv; x1.w *= inv;
    *(float4*)p = x0;
    *(float4*)(p + 4) = x1;
}

// ---------------- rowwise LayerNorm over C=128 (+optional residual) ----------------
__global__ __launch_bounds__(128) void ln128(
    const float* __restrict__ x, const float* __restrict__ g,
    const float* __restrict__ bb, const float* __restrict__ res,
    float* __restrict__ y)
{
    const int tid = threadIdx.x;
    const size_t base = (size_t)blockIdx.x * C_;
    __shared__ float red[128];
    float v = x[base + tid];
    red[tid] = v; __syncthreads();
    for (int s = 64; s > 0; s >>= 1) {
        if (tid < s) red[tid] += red[tid + s];
        __syncthreads();
    }
    float mean = red[0] * (1.0f / C_); __syncthreads();
    float d = v - mean;
    red[tid] = d * d; __syncthreads();
    for (int s = 64; s > 0; s >>= 1) {
        if (tid < s) red[tid] += red[tid + s];
        __syncthreads();
    }
    float var = red[0] * (1.0f / C_);
    float o = d * rsqrtf(var + 1e-5f) * g[tid] + bb[tid];
    if (res) o += res[base + tid];
    y[base + tid] = o;
}

// ---------------- launch ----------------
extern "C" void kernel_launch(void* const* d_in, const int* in_sizes, int n_in,
                              void* d_out, int out_size) {
    const float* source = (const float*)d_in[0];
    const float* target = (const float*)d_in[1];
    const float* Wq = (const float*)d_in[2];
    const float* Wk = (const float*)d_in[3];
    const float* Wv = (const float*)d_in[4];
    const float* Wm = (const float*)d_in[5];
    const float* g1 = (const float*)d_in[6];
    const float* b1 = (const float*)d_in[7];
    const float* W1 = (const float*)d_in[8];
    const float* W2 = (const float*)d_in[9];
    const float* g2 = (const float*)d_in[10];
    const float* b2 = (const float*)d_in[11];
    const float* mask = (const float*)d_in[12];
    float* out = (float*)d_out;

    float *sc, *ao, *t1, *msg, *hid;
    cudaGetSymbolAddress((void**)&sc,  g_sc);
    cudaGetSymbolAddress((void**)&ao,  g_ao);
    cudaGetSymbolAddress((void**)&t1,  g_t1);
    cudaGetSymbolAddress((void**)&msg, g_msg);
    cudaGetSymbolAddress((void**)&hid, g_hid);

    // 1. Q/K/V projections (tensor core, tf32)
    qkv_tf32<<<dim3(1, MT/128, 3), 256>>>(source, target, Wq, Wk, Wv);
    // 2. window scores (shift-gather fused)
    win_scores_tf32<<<dim3(2, 2, B_*NWIN), 256>>>(mask);
    // 3. softmax (warp per row)
    softmax_warp<<<(B_*NWIN*WT)/8, 256>>>(sc);
    // 4. attn @ V (scatter-unshift fused)
    win_av_tf32<<<dim3(1, 2, B_*NWIN), 256>>>();
    // 5. message = LN1(attn_out @ Wm)
    gemm_tf32<<<dim3(1, MT/128), 256>>>(ao, Wm, t1, C_, C_);
    ln128<<<MT, 128>>>(t1, g1, b1, nullptr, msg);
    // 6. FFN
    ffn1_tf32<<<dim3(HID_/128, MT/128), 256>>>(source, W1);
    gemm_tf32<<<dim3(1, MT/128), 256>>>(hid, W2, t1, C_, HID_);
    // 7. out = source + LN2(ffn)
    ln128<<<MT, 128>>>(t1, g2, b2, source, out);
}

// round 15
// speedup vs baseline: 1.1361x; 1.1361x over previous
#include <cuda_runtime.h>
#include <math.h>

#define B_   2
#define HGT  128
#define WID  128
#define C_   128
#define NWIN 64
#define WT   256
#define LTOK (HGT*WID)
#define MT   (B_*LTOK)     // 32768
#define HID_ 1024
#define SCALE 0.08838834764831845f

#define PAD  20            // smem row stride (floats); 80B = 16B-aligned for cp.async
#define BK   16
#define TSZ  (128*PAD)
#define DSM_BYTES (3*2*TSZ*4)   // 3 stages x (A+B) = 61440 B

// ---------------- device scratch ----------------
static __device__ float g_srcr[MT*C_];
static __device__ float g_tgtr[MT*C_];
static __device__ float g_q [MT*C_];
static __device__ float g_k [MT*C_];
static __device__ float g_v [MT*C_];
static __device__ float g_sc[(size_t)B_*NWIN*WT*WT];
static __device__ float g_ao[MT*C_];
static __device__ float g_t1[MT*C_];
static __device__ float g_msg[MT*C_];
static __device__ float g_hid[(size_t)MT*HID_];
static __device__ float g_wts[458752];   // transposed+rounded weights
#define WQT 0
#define WKT 16384
#define WVT 32768
#define WMT 49152
#define W1TO 65536
#define W2TO 327680

__device__ __forceinline__ int tok_off(int b, int n, int i) {
    int wy = n >> 3, wx = n & 7;
    int gh = ((wy << 4) + (i >> 4) + 8) & 127;
    int gw = ((wx << 4) + (i & 15) + 8) & 127;
    return ((b * HGT + gh) * WID + gw) * C_;
}
__device__ __forceinline__ float tf32r(float x) {
    unsigned u; asm("cvt.rna.tf32.f32 %0, %1;" : "=r"(u) : "f"(x));
    return __uint_as_float(u);
}

// ---------------- cp.async primitives ----------------
__device__ __forceinline__ void cp16(float* dst, const float* src) {
    unsigned d = (unsigned)__cvta_generic_to_shared(dst);
    asm volatile("cp.async.cg.shared.global [%0], [%1], 16;\n" :: "r"(d), "l"(src));
}
__device__ __forceinline__ void cp_commit() {
    asm volatile("cp.async.commit_group;\n");
}
template<int N> __device__ __forceinline__ void cp_wait() {
    asm volatile("cp.async.wait_group %0;\n" :: "n"(N));
}

// thread tid covers tile row (tid>>1), 32B half-row (tid&1): two 16B chunks
__device__ __forceinline__ void issueA(float* S, const float* A, int lda, int k0, int tid) {
    const float* p = A + (size_t)(tid >> 1) * lda + k0 + (tid & 1) * 8;
    float* s = S + (tid >> 1) * PAD + (tid & 1) * 8;
    cp16(s, p); cp16(s + 4, p + 4);
}
__device__ __forceinline__ void issueA_gather(float* S, const float* X, const int* __restrict__ off,
                                              int k0, int tid) {
    const float* p = X + off[tid >> 1] + k0 + (tid & 1) * 8;
    float* s = S + (tid >> 1) * PAD + (tid & 1) * 8;
    cp16(s, p); cp16(s + 4, p + 4);
}

// ---------------- mma compute: plain layout, 2 k8 steps ----------------
__device__ __forceinline__ void mma_compute(const float* __restrict__ As,
                                            const float* __restrict__ Bs,
                                            float (&acc)[4][4][4],
                                            int wm0, int wn0, int lane)
{
    const int r = lane >> 2, c = lane & 3;
    #pragma unroll
    for (int ks = 0; ks < 2; ++ks) {
        const int k = ks * 8;
        unsigned a[4][4], bf[4][2];
        #pragma unroll
        for (int mt = 0; mt < 4; ++mt) {
            const float* p = As + (wm0 + mt*16 + r)*PAD + k + c;
            a[mt][0] = __float_as_uint(p[0]);
            a[mt][1] = __float_as_uint(p[8*PAD]);
            a[mt][2] = __float_as_uint(p[4]);
            a[mt][3] = __float_as_uint(p[8*PAD + 4]);
        }
        #pragma unroll
        for (int nt = 0; nt < 4; ++nt) {
            const float* p = Bs + (wn0 + nt*8 + r)*PAD + k + c;
            bf[nt][0] = __float_as_uint(p[0]);
            bf[nt][1] = __float_as_uint(p[4]);
        }
        #pragma unroll
        for (int mt = 0; mt < 4; ++mt)
            #pragma unroll
            for (int nt = 0; nt < 4; ++nt)
                asm volatile(
                  "mma.sync.aligned.m16n8k8.row.col.f32.tf32.tf32.f32 "
                  "{%0,%1,%2,%3},{%4,%5,%6,%7},{%8,%9},{%0,%1,%2,%3};"
                  : "+f"(acc[mt][nt][0]), "+f"(acc[mt][nt][1]),
                    "+f"(acc[mt][nt][2]), "+f"(acc[mt][nt][3])
                  : "r"(a[mt][0]), "r"(a[mt][1]), "r"(a[mt][2]), "r"(a[mt][3]),
                    "r"(bf[nt][0]), "r"(bf[nt][1]));
    }
}

// ---------------- 3-stage pipeline skeleton ----------------
template<class FIssue>
__device__ __forceinline__ void pipeline_loop(float* As, float* Bs, int NIT,
        float (&acc)[4][4][4], int wm0, int wn0, int lane, FIssue issue)
{
    issue(0, 0);  cp_commit();
    issue(1, BK); cp_commit();
    int buf = 0;
    for (int it = 0; it < NIT; ++it) {
        cp_wait<1>();
        __syncthreads();
        if (it + 2 < NIT) {
            int nb = (buf + 2 >= 3) ? buf - 1 : buf + 2;
            issue(nb, (it + 2) * BK);
        }
        cp_commit();
        mma_compute(As + buf*TSZ, Bs + buf*TSZ, acc, wm0, wn0, lane);
        buf = (buf + 1 == 3) ? 0 : buf + 1;
    }
}

// ---------------- store ----------------
template<int RND>
__device__ __forceinline__ void store_plain(float* __restrict__ Cg, int ldc, int bm0, int bn0,
                                            const float (&acc)[4][4][4], int wm0, int wn0, int lane)
{
    const int r = lane >> 2, q2 = (lane & 3) * 2;
    #pragma unroll
    for (int mt = 0; mt < 4; ++mt) {
        const int row = bm0 + wm0 + mt*16 + r;
        #pragma unroll
        for (int nt = 0; nt < 4; ++nt) {
            const int col = bn0 + wn0 + nt*8 + q2;
            float v0 = acc[mt][nt][0], v1 = acc[mt][nt][1];
            float v2 = acc[mt][nt][2], v3 = acc[mt][nt][3];
            if (RND) { v0 = tf32r(v0); v1 = tf32r(v1); v2 = tf32r(v2); v3 = tf32r(v3); }
            *(float2*)&Cg[(size_t)row * ldc + col]       = make_float2(v0, v1);
            *(float2*)&Cg[(size_t)(row + 8) * ldc + col] = make_float2(v2, v3);
        }
    }
}

// ---------------- QKV (cp.async): A = rounded src/tgt, B = transposed weights ----------------
__global__ __launch_bounds__(256) void qkv_cp()
{
    extern __shared__ __align__(16) float dsm[];
    float* As = dsm;
    float* Bs = dsm + 3*TSZ;
    const int z = blockIdx.z;
    const float* A  = (z == 0) ? g_srcr : g_tgtr;
    const float* BT = g_wts + ((z == 0) ? WQT : (z == 1 ? WKT : WVT));
    float* O = (z == 0) ? g_q : (z == 1 ? g_k : g_v);

    const int tid = threadIdx.x, lane = tid & 31, wid = tid >> 5;
    const int wm0 = (wid >> 2) * 64, wn0 = (wid & 3) * 32;
    const int bm0 = blockIdx.y * 128;
    const float* Ab = A + (size_t)bm0 * C_;
    float acc[4][4][4] = {};

    auto issue = [&](int s, int k0) {
        issueA(As + s*TSZ, Ab, C_, k0, tid);
        issueA(Bs + s*TSZ, BT, C_, k0, tid);
    };
    pipeline_loop(As, Bs, C_/BK, acc, wm0, wn0, lane, issue);
    store_plain<1>(O, C_, bm0, 0, acc, wm0, wn0, lane);   // round: GEMM input later
}

// ---------------- generic GEMM (cp.async): C = A @ BT^T, N=128 ----------------
__global__ __launch_bounds__(256) void gemm_cp(const float* __restrict__ A,
                                               const float* __restrict__ BT,
                                               float* __restrict__ Cg, int K)
{
    extern __shared__ __align__(16) float dsm[];
    float* As = dsm;
    float* Bs = dsm + 3*TSZ;
    const int tid = threadIdx.x, lane = tid & 31, wid = tid >> 5;
    const int wm0 = (wid >> 2) * 64, wn0 = (wid & 3) * 32;
    const int bm0 = blockIdx.y * 128;
    const float* Ab = A + (size_t)bm0 * K;
    float acc[4][4][4] = {};

    auto issue = [&](int s, int k0) {
        issueA(As + s*TSZ, Ab, K, k0, tid);
        issueA(Bs + s*TSZ, BT, K, k0, tid);
    };
    pipeline_loop(As, Bs, K/BK, acc, wm0, wn0, lane, issue);
    store_plain<0>(Cg, C_, bm0, 0, acc, wm0, wn0, lane);
}

// ---------------- window scores (cp.async gather): S = Qw Kw^T * scale + mask ----------------
__global__ __launch_bounds__(256) void scores_cp(const float* __restrict__ mask)
{
    extern __shared__ __align__(16) float dsm[];
    float* As = dsm;
    float* Bs = dsm + 3*TSZ;
    __shared__ int offQ[128], offK[128];
    const int bw = blockIdx.z, b = bw >> 6, n = bw & 63;
    const int bi0 = blockIdx.y * 128, bj0 = blockIdx.x * 128;
    const int tid = threadIdx.x, lane = tid & 31, wid = tid >> 5;
    const int wm0 = (wid >> 2) * 64, wn0 = (wid & 3) * 32;

    if (tid < 128) offQ[tid] = tok_off(b, n, bi0 + tid);
    else           offK[tid - 128] = tok_off(b, n, bj0 + tid - 128);
    __syncthreads();

    float acc[4][4][4] = {};
    auto issue = [&](int s, int k0) {
        issueA_gather(As + s*TSZ, g_q, offQ, k0, tid);
        issueA_gather(Bs + s*TSZ, g_k, offK, k0, tid);
    };
    pipeline_loop(As, Bs, C_/BK, acc, wm0, wn0, lane, issue);

    const int r = lane >> 2, q2 = (lane & 3) * 2;
    #pragma unroll
    for (int mt = 0; mt < 4; ++mt)
        #pragma unroll
        for (int nt = 0; nt < 4; ++nt) {
            const int col = bj0 + wn0 + nt*8 + q2;
            #pragma unroll
            for (int hh = 0; hh < 2; ++hh) {
                const int row = bi0 + wm0 + mt*16 + r + hh*8;
                const size_t sidx = ((size_t)bw * WT + row) * WT + col;
                const size_t midx = ((size_t)n  * WT + row) * WT + col;
                float2 mk = *(const float2*)&mask[midx];
                *(float2*)&g_sc[sidx] =
                    make_float2(acc[mt][nt][2*hh]   * SCALE + mk.x,
                                acc[mt][nt][2*hh+1] * SCALE + mk.y);
            }
        }
}

// ---------------- FFN1 (cp.async): H = gelu([src|msg] @ W1) ----------------
__global__ __launch_bounds__(256) void ffn1_cp()
{
    extern __shared__ __align__(16) float dsm[];
    float* As = dsm;
    float* Bs = dsm + 3*TSZ;
    const int tid = threadIdx.x, lane = tid & 31, wid = tid >> 5;
    const int wm0 = (wid >> 2) * 64, wn0 = (wid & 3) * 32;
    const int bm0 = blockIdx.y * 128, bn0 = blockIdx.x * 128;
    const float* A0 = g_srcr + (size_t)bm0 * C_;
    const float* A1 = g_msg  + (size_t)bm0 * C_;
    const float* BT = g_wts + W1TO + (size_t)bn0 * 256;
    float acc[4][4][4] = {};

    auto issue = [&](int s, int k0) {
        const float* Ae = (k0 < C_) ? A0 : A1;
        issueA(As + s*TSZ, Ae, C_, k0 & (C_-1), tid);
        issueA(Bs + s*TSZ, BT, 256, k0, tid);
    };
    pipeline_loop(As, Bs, 256/BK, acc, wm0, wn0, lane, issue);

    const int r = lane >> 2, q2 = (lane & 3) * 2;
    #pragma unroll
    for (int mt = 0; mt < 4; ++mt)
        #pragma unroll
        for (int nt = 0; nt < 4; ++nt) {
            const int col = bn0 + wn0 + nt*8 + q2;
            #pragma unroll
            for (int hh = 0; hh < 2; ++hh) {
                const int row = bm0 + wm0 + mt*16 + r + hh*8;
                float x0 = acc[mt][nt][2*hh], x1 = acc[mt][nt][2*hh+1];
                float gg0 = 0.5f * x0 * (1.0f + erff(x0 * 0.70710678118654752f));
                float gg1 = 0.5f * x1 * (1.0f + erff(x1 * 0.70710678118654752f));
                *(float2*)&g_hid[(size_t)row * HID_ + col] =
                    make_float2(tf32r(gg0), tf32r(gg1));
            }
        }
}

// ---------------- win_av: register-staged (V transpose gather), plain layout ----------------
__device__ __forceinline__ void ldA_reg(const float* __restrict__ A, int lda, int k0,
                                        int tid, float4& v0, float4& v1) {
    const float* p = A + (size_t)(tid >> 1) * lda + k0 + (tid & 1) * 8;
    v0 = *(const float4*)p; v1 = *(const float4*)(p + 4);
}
__device__ __forceinline__ void stA_reg(float* __restrict__ S, int tid, float4 v0, float4 v1) {
    float* p = S + (tid >> 1) * PAD + (tid & 1) * 8;
    p[0]=tf32r(v0.x); p[1]=tf32r(v0.y); p[2]=tf32r(v0.z); p[3]=tf32r(v0.w);
    p[4]=tf32r(v1.x); p[5]=tf32r(v1.y); p[6]=tf32r(v1.z); p[7]=tf32r(v1.w);
}
__device__ __forceinline__ void ldBT_gather_reg(const float* __restrict__ V, const int* __restrict__ off,
                                                int k0, int tid, float rb[8]) {
    const int kr = tid >> 5, lane = tid & 31;
    const float* p0 = V + off[k0 + kr]     + lane;
    const float* p1 = V + off[k0 + kr + 8] + lane;
    #pragma unroll
    for (int i = 0; i < 4; ++i) { rb[i] = p0[32*i]; rb[4+i] = p1[32*i]; }
}
__device__ __forceinline__ void stBT_reg(float* __restrict__ S, int tid, const float rb[8]) {
    const int kr = tid >> 5, lane = tid & 31;
    #pragma unroll
    for (int i = 0; i < 4; ++i) {
        S[(lane + 32*i)*PAD + kr    ] = tf32r(rb[i]);
        S[(lane + 32*i)*PAD + kr + 8] = tf32r(rb[4+i]);
    }
}

__global__ __launch_bounds__(256) void win_av_man()
{
    __shared__ __align__(16) float As2[2*TSZ], Bs2[2*TSZ];
    __shared__ int offV[256];
    const int bw = blockIdx.z, b = bw >> 6, n = bw & 63;
    const int bi0 = blockIdx.y * 128;
    const int tid = threadIdx.x, lane = tid & 31, wid = tid >> 5;
    const int wm0 = (wid >> 2) * 64, wn0 = (wid & 3) * 32;

    offV[tid] = tok_off(b, n, tid);
    __syncthreads();

    const float* P = g_sc + ((size_t)bw * WT + bi0) * WT;
    float acc[4][4][4] = {};
    float4 a0, a1; float rb[8];
    ldA_reg(P, WT, 0, tid, a0, a1); ldBT_gather_reg(g_v, offV, 0, tid, rb);
    stA_reg(As2, tid, a0, a1); stBT_reg(Bs2, tid, rb);
    __syncthreads();
    int buf = 0;
    for (int k0 = BK; k0 < WT; k0 += BK) {
        ldA_reg(P, WT, k0, tid, a0, a1); ldBT_gather_reg(g_v, offV, k0, tid, rb);
        mma_compute(As2 + buf*TSZ, Bs2 + buf*TSZ, acc, wm0, wn0, lane);
        stA_reg(As2 + (buf^1)*TSZ, tid, a0, a1); stBT_reg(Bs2 + (buf^1)*TSZ, tid, rb);
        __syncthreads();
        buf ^= 1;
    }
    mma_compute(As2 + buf*TSZ, Bs2 + buf*TSZ, acc, wm0, wn0, lane);

    const int r = lane >> 2, q2 = (lane & 3) * 2;
    #pragma unroll
    for (int mt = 0; mt < 4; ++mt)
        #pragma unroll
        for (int hh = 0; hh < 2; ++hh) {
            const int lrow = wm0 + mt*16 + r + hh*8;
            const int ro = offV[bi0 + lrow];
            #pragma unroll
            for (int nt = 0; nt < 4; ++nt) {
                const int col = wn0 + nt*8 + q2;
                *(float2*)&g_ao[ro + col] =
                    make_float2(tf32r(acc[mt][nt][2*hh]), tf32r(acc[mt][nt][2*hh+1]));
            }
        }
}

// ---------------- prep kernels ----------------
__global__ __launch_bounds__(256) void round4(const float4* __restrict__ in,
                                              float4* __restrict__ out) {
    int i = blockIdx.x * 256 + threadIdx.x;
    float4 v = in[i];
    v.x = tf32r(v.x); v.y = tf32r(v.y); v.z = tf32r(v.z); v.w = tf32r(v.w);
    out[i] = v;
}
// out[Ccols][R] = tf32r(in[R][Ccols])
__global__ void transpose_rnd(const float* __restrict__ in, float* __restrict__ out,
                              int R, int Ccols) {
    __shared__ float t[32][33];
    const int bx = blockIdx.x * 32, by = blockIdx.y * 32;
    const int x = threadIdx.x, y = threadIdx.y;
    #pragma unroll
    for (int i = 0; i < 32; i += 8)
        t[y + i][x] = in[(size_t)(by + y + i) * Ccols + bx + x];
    __syncthreads();
    #pragma unroll
    for (int i = 0; i < 32; i += 8)
        out[(size_t)(bx + y + i) * R + by + x] = tf32r(t[x][y + i]);
}

// ---------------- warp-per-row softmax over 256 (in place) ----------------
__global__ __launch_bounds__(256) void softmax_warp(float* __restrict__ sc) {
    const int row  = blockIdx.x * 8 + (threadIdx.x >> 5);
    const int lane = threadIdx.x & 31;
    float* p = sc + (size_t)row * WT + lane * 8;
    float4 x0 = *(const float4*)p;
    float4 x1 = *(const float4*)(p + 4);
    float m = fmaxf(fmaxf(fmaxf(x0.x, x0.y), fmaxf(x0.z, x0.w)),
                    fmaxf(fmaxf(x1.x, x1.y), fmaxf(x1.z, x1.w)));
    #pragma unroll
    for (int s = 16; s > 0; s >>= 1) m = fmaxf(m, __shfl_xor_sync(0xffffffffu, m, s));
    x0.x = __expf(x0.x - m); x0.y = __expf(x0.y - m);
    x0.z = __expf(x0.z - m); x0.w = __expf(x0.w - m);
    x1.x = __expf(x1.x - m); x1.y = __expf(x1.y - m);
    x1.z = __expf(x1.z - m); x1.w = __expf(x1.w - m);
    float sum = x0.x + x0.y + x0.z + x0.w + x1.x + x1.y + x1.z + x1.w;
    #pragma unroll
    for (int s = 16; s > 0; s >>= 1) sum += __shfl_xor_sync(0xffffffffu, sum, s);
    const float inv = 1.0f / sum;
    x0.x *= inv; x0.y *= inv; x0.z *= inv; x0.w *= inv;
    x1.x *= inv; x1.y *= inv; x1.z *= inv; x1.w *= inv;
    *(float4*)p = x0;
    *(float4*)(p + 4) = x1;
}

// ---------------- rowwise LayerNorm over C=128 (+residual, or tf32 round) ----------------
__global__ __launch_bounds__(128) void ln128(
    const float* __restrict__ x, const float* __restrict__ g,
    const float* __restrict__ bb, const float* __restrict__ res,
    float* __restrict__ y)
{
    const int tid = threadIdx.x;
    const size_t base = (size_t)blockIdx.x * C_;
    __shared__ float red[128];
    float v = x[base + tid];
    red[tid] = v; __syncthreads();
    for (int s = 64; s > 0; s >>= 1) {
        if (tid < s) red[tid] += red[tid + s];
        __syncthreads();
    }
    float mean = red[0] * (1.0f / C_); __syncthreads();
    float d = v - mean;
    red[tid] = d * d; __syncthreads();
    for (int s = 64; s > 0; s >>= 1) {
        if (tid < s) red[tid] += red[tid + s];
        __syncthreads();
    }
    float var = red[0] * (1.0f / C_);
    float o = d * rsqrtf(var + 1e-5f) * g[tid] + bb[tid];
    if (res) o += res[base + tid];
    else     o = tf32r(o);          // msg feeds a cp.async GEMM -> pre-round
    y[base + tid] = o;
}

// ---------------- launch ----------------
extern "C" void kernel_launch(void* const* d_in, const int* in_sizes, int n_in,
                              void* d_out, int out_size) {
    const float* source = (const float*)d_in[0];
    const float* target = (const float*)d_in[1];
    const float* Wq = (const float*)d_in[2];
    const float* Wk = (const float*)d_in[3];
    const float* Wv = (const float*)d_in[4];
    const float* Wm = (const float*)d_in[5];
    const float* g1 = (const float*)d_in[6];
    const float* b1 = (const float*)d_in[7];
    const float* W1 = (const float*)d_in[8];
    const float* W2 = (const float*)d_in[9];
    const float* g2 = (const float*)d_in[10];
    const float* b2 = (const float*)d_in[11];
    const float* mask = (const float*)d_in[12];
    float* out = (float*)d_out;

    float *srcr, *tgtr, *sc, *ao, *t1, *msg, *hid, *wts;
    cudaGetSymbolAddress((void**)&srcr, g_srcr);
    cudaGetSymbolAddress((void**)&tgtr, g_tgtr);
    cudaGetSymbolAddress((void**)&sc,   g_sc);
    cudaGetSymbolAddress((void**)&ao,   g_ao);
    cudaGetSymbolAddress((void**)&t1,   g_t1);
    cudaGetSymbolAddress((void**)&msg,  g_msg);
    cudaGetSymbolAddress((void**)&hid,  g_hid);
    cudaGetSymbolAddress((void**)&wts,  g_wts);

    cudaFuncSetAttribute(qkv_cp,   cudaFuncAttributeMaxDynamicSharedMemorySize, DSM_BYTES);
    cudaFuncSetAttribute(gemm_cp,  cudaFuncAttributeMaxDynamicSharedMemorySize, DSM_BYTES);
    cudaFuncSetAttribute(scores_cp,cudaFuncAttributeMaxDynamicSharedMemorySize, DSM_BYTES);
    cudaFuncSetAttribute(ffn1_cp,  cudaFuncAttributeMaxDynamicSharedMemorySize, DSM_BYTES);

    // 0. prep: round activations, transpose+round weights
    round4<<<MT*C_/1024, 256>>>((const float4*)source, (float4*)srcr);
    round4<<<MT*C_/1024, 256>>>((const float4*)target, (float4*)tgtr);
    dim3 tb(32, 8);
    transpose_rnd<<<dim3(4, 4),  tb>>>(Wq, wts + WQT, 128, 128);
    transpose_rnd<<<dim3(4, 4),  tb>>>(Wk, wts + WKT, 128, 128);
    transpose_rnd<<<dim3(4, 4),  tb>>>(Wv, wts + WVT, 128, 128);
    transpose_rnd<<<dim3(4, 4),  tb>>>(Wm, wts + WMT, 128, 128);
    transpose_rnd<<<dim3(32, 8), tb>>>(W1, wts + W1TO, 256, 1024);
    transpose_rnd<<<dim3(4, 32), tb>>>(W2, wts + W2TO, 1024, 128);

    // 1. Q/K/V projections
    qkv_cp<<<dim3(1, MT/128, 3), 256, DSM_BYTES>>>();
    // 2. window scores (shift-gather fused)
    scores_cp<<<dim3(2, 2, B_*NWIN), 256, DSM_BYTES>>>(mask);
    // 3. softmax
    softmax_warp<<<(B_*NWIN*WT)/8, 256>>>(sc);
    // 4. attn @ V (scatter-unshift fused)
    win_av_man<<<dim3(1, 2, B_*NWIN), 256>>>();
    // 5. message = LN1(attn_out @ Wm)
    gemm_cp<<<dim3(1, MT/128), 256, DSM_BYTES>>>(ao, wts + WMT, t1, C_);
    ln128<<<MT, 128>>>(t1, g1, b1, nullptr, msg);
    // 6. FFN
    ffn1_cp<<<dim3(HID_/128, MT/128), 256, DSM_BYTES>>>();
    gemm_cp<<<dim3(1, MT/128), 256, DSM_BYTES>>>(hid, wts + W2TO, t1, HID_);
    // 7. out = source + LN2(ffn)
    ln128<<<MT, 128>>>(t1, g2, b2, source, out);
}